// round 10
// baseline (speedup 1.0000x reference)
#include <cuda_runtime.h>
#include <cuda.h>
#include <math_constants.h>
#include <cstdint>

typedef unsigned int u32;
typedef unsigned long long u64;

// r = softmax( (q @ k) * 0.1 , -1) @ v ; B=8, S=2048, D=Dv=1024, fp32.
// Round 10: TMA bulk tile loads (UTMALDG) + single-thread producer/MMA
// decoupled over a 3-slot ring. tcgen05 tf32 SS MMAs, 256x256 tile.

#if defined(__CUDA_ARCH_FEAT_SM103_ALL) || defined(__CUDA_ARCH_FEAT_SM100_ALL) || \
    defined(__CUDA_ARCH_SPECIFIC__)
#define HAS_TCGEN05 1
#else
#define HAS_TCGEN05 0
#endif

#define ATT_B 8
#define ATT_S 2048
#define ATT_D 1024

__device__ float g_scores[(size_t)ATT_B * ATT_S * ATT_S];
__device__ float g_qr[(size_t)ATT_B * ATT_S * ATT_D];
__device__ float g_kT[(size_t)ATT_B * ATT_S * ATT_D];
__device__ float g_vT[(size_t)ATT_B * ATT_D * ATT_S];

// ---------------- PTX helpers ----------------
__device__ __forceinline__ u32 smem_u32(const void* p) {
    u32 a;
    asm("{ .reg .u64 t; cvta.to.shared.u64 t, %1; cvt.u32.u64 %0, t; }"
        : "=r"(a) : "l"(p));
    return a;
}
__device__ __forceinline__ u32 cvt_tf32(float x) {
    u32 r;
    asm("cvt.rn.tf32.f32 %0, %1;" : "=r"(r) : "f"(x));
    return r;
}
__device__ __forceinline__ void mbar_init(u32 mbar, u32 cnt) {
    asm volatile("mbarrier.init.shared.b64 [%0], %1;" :: "r"(mbar), "r"(cnt) : "memory");
}
__device__ __forceinline__ void mbar_expect_tx(u32 mbar, u32 bytes) {
    asm volatile("mbarrier.arrive.expect_tx.shared.b64 _, [%0], %1;"
                 :: "r"(mbar), "r"(bytes) : "memory");
}
__device__ __forceinline__ void mbar_wait(u32 mbar, u32 parity) {
    asm volatile(
        "{ .reg .pred P;\n"
        "L%=: mbarrier.try_wait.parity.acquire.cta.shared::cta.b64 P, [%0], %1, 0x989680;\n"
        "@P bra D%=;\n"
        "bra L%=;\n"
        "D%=: }\n"
        :: "r"(mbar), "r"(parity) : "memory");
}
__device__ __forceinline__ void tma_load_3d(u32 smem_dst, const CUtensorMap* tm,
                                            int cx, int cy, int cz, u32 mbar) {
    asm volatile(
        "cp.async.bulk.tensor.3d.shared::cta.global.tile.mbarrier::complete_tx::bytes "
        "[%0], [%1, {%2, %3, %4}], [%5];"
        :: "r"(smem_dst), "l"(tm), "r"(cx), "r"(cy), "r"(cz), "r"(mbar)
        : "memory");
}

#if HAS_TCGEN05
__device__ __forceinline__ void tmem_alloc(u32 smem_dst, u32 ncols) {
    asm volatile("tcgen05.alloc.cta_group::1.sync.aligned.shared::cta.b32 [%0], %1;"
                 :: "r"(smem_dst), "r"(ncols) : "memory");
}
__device__ __forceinline__ void tmem_relinquish() {
    asm volatile("tcgen05.relinquish_alloc_permit.cta_group::1.sync.aligned;");
}
__device__ __forceinline__ void tmem_dealloc(u32 tmem, u32 ncols) {
    asm volatile("tcgen05.dealloc.cta_group::1.sync.aligned.b32 %0, %1;"
                 :: "r"(tmem), "r"(ncols));
}
__device__ __forceinline__ void mma_tf32_ss(u32 d_tmem, u64 ad, u64 bd, u32 idesc, u32 en) {
    asm volatile(
        "{ .reg .pred p; setp.ne.u32 p, %4, 0;\n"
        "tcgen05.mma.cta_group::1.kind::tf32 [%0], %1, %2, %3, {%5,%5,%5,%5}, p;\n }"
        :: "r"(d_tmem), "l"(ad), "l"(bd), "r"(idesc), "r"(en), "r"(0u) : "memory");
}
__device__ __forceinline__ void mma_commit(u32 mbar) {
    asm volatile(
        "tcgen05.commit.cta_group::1.mbarrier::arrive::one.shared::cluster.b64 [%0];"
        :: "r"(mbar) : "memory");
}
__device__ __forceinline__ void tc_fence_after() {
    asm volatile("tcgen05.fence::after_thread_sync;" ::: "memory");
}
__device__ __forceinline__ void tmem_ld32(u32* r, u32 tmem) {
    asm volatile(
        "tcgen05.ld.sync.aligned.32x32b.x32.b32 "
        "{%0,%1,%2,%3,%4,%5,%6,%7,%8,%9,%10,%11,%12,%13,%14,%15,"
        "%16,%17,%18,%19,%20,%21,%22,%23,%24,%25,%26,%27,%28,%29,%30,%31}, [%32];"
        : "=r"(r[0]), "=r"(r[1]), "=r"(r[2]), "=r"(r[3]),
          "=r"(r[4]), "=r"(r[5]), "=r"(r[6]), "=r"(r[7]),
          "=r"(r[8]), "=r"(r[9]), "=r"(r[10]), "=r"(r[11]),
          "=r"(r[12]), "=r"(r[13]), "=r"(r[14]), "=r"(r[15]),
          "=r"(r[16]), "=r"(r[17]), "=r"(r[18]), "=r"(r[19]),
          "=r"(r[20]), "=r"(r[21]), "=r"(r[22]), "=r"(r[23]),
          "=r"(r[24]), "=r"(r[25]), "=r"(r[26]), "=r"(r[27]),
          "=r"(r[28]), "=r"(r[29]), "=r"(r[30]), "=r"(r[31])
        : "r"(tmem));
}
__device__ __forceinline__ void tmem_wait_ld() {
    asm volatile("tcgen05.wait::ld.sync.aligned;" ::: "memory");
}
#endif  // HAS_TCGEN05

static constexpr u64 DESC_BASE =
    (2ull << 61) | (1ull << 46) | (64ull << 32) | (1ull << 16);
__device__ __forceinline__ u64 mk_desc(u32 addr) {
    return DESC_BASE | ((u64)(addr >> 4) & 0x3FFF);
}

// idesc kind::tf32: dtype=F32, atype=btype=TF32, N=128, M=128
static constexpr u32 IDESC_TF32 =
    (1u << 4) | (2u << 7) | (2u << 10) | ((128u / 8) << 17) | ((128u / 16) << 24);

#define TK 32
#define TM_TILE 256
#define TN_TILE 256
#define A_BYTES 32768
#define B_BYTES 32768
#define STAGE_BYTES (A_BYTES + B_BYTES)   // 64KB
#define STAGES 3
#define SMEM_CTRL 2048
#define SMEM_DYN (SMEM_CTRL + STAGES * STAGE_BYTES)   // 198,656 B

// ---------------------------------------------------------------------------
// TMA + tcgen05 tf32 GEMM:  C[M,N] = alpha * A[M,K] @ BT[N,K]^T
// Tensor maps: box [32 floats, 256 rows], SW128.
// ---------------------------------------------------------------------------
__global__ __launch_bounds__(128) void gemm_tf32_tma(
    const __grid_constant__ CUtensorMap tmA,
    const __grid_constant__ CUtensorMap tmB,
    float* __restrict__ C, int K, int ldc, float alpha, long long strideC)
{
#if HAS_TCGEN05
    extern __shared__ char smem[];
    const u32 smem_base = smem_u32(smem);
    const u32 tiles_addr = (smem_base + 1024 + 1023) & ~1023u;

    const int tid = threadIdx.x;
    const int wid = tid >> 5;
    const int lid = tid & 31;

    const int b = blockIdx.z;
    C += (long long)b * strideC;

    const int row0 = blockIdx.y * TM_TILE;
    const int col0 = blockIdx.x * TN_TILE;

    // ctrl: tmem ptr @0, full[3] @8, done[3] @32, final @56
    const u32 mb_full = smem_base + 8;
    const u32 mb_done = smem_base + 32;
    const u32 mbarF   = smem_base + 56;

    if (tid == 0) {
        #pragma unroll
        for (int s = 0; s < STAGES; s++) {
            mbar_init(mb_full + 8 * s, 1);
            mbar_init(mb_done + 8 * s, 1);
        }
        mbar_init(mbarF, 1);
    }
    if (wid == 0) {
        tmem_alloc(smem_base + 0, 512);
        tmem_relinquish();
    }
    __syncthreads();
    u32 tmem;
    asm volatile("ld.shared.b32 %0, [%1];" : "=r"(tmem) : "r"(smem_base + 0));

    const int KT = K / TK;

    if (tid == 0) {
        // ---------------- TMA producer ----------------
        u32 phases = 0;
        for (int j = 0; j < KT; j++) {
            const int slot = j % STAGES;
            if (j >= STAGES) {
                mbar_wait(mb_done + 8 * slot, (phases >> slot) & 1);
                phases ^= (1u << slot);
            }
            const u32 At = tiles_addr + slot * STAGE_BYTES;
            const u32 Bt = At + A_BYTES;
            mbar_expect_tx(mb_full + 8 * slot, STAGE_BYTES);
            tma_load_3d(At, &tmA, j * TK, row0, b, mb_full + 8 * slot);
            tma_load_3d(Bt, &tmB, j * TK, col0, b, mb_full + 8 * slot);
        }
    } else if (tid == 32) {
        // ---------------- MMA consumer ----------------
        u32 phases = 0;
        for (int i = 0; i < KT; i++) {
            const int slot = i % STAGES;
            mbar_wait(mb_full + 8 * slot, (phases >> slot) & 1);
            phases ^= (1u << slot);

            const u32 At = tiles_addr + slot * STAGE_BYTES;
            const u64 a0 = mk_desc(At);
            const u64 a1 = mk_desc(At + 16384);
            const u64 b0 = mk_desc(At + A_BYTES);
            const u64 b1 = mk_desc(At + A_BYTES + 16384);
            #pragma unroll
            for (int sub = 0; sub < 4; sub++) {
                const u32 en = (i | sub) != 0;
                const u64 o = sub * 2;
                mma_tf32_ss(tmem,       a0 + o, b0 + o, IDESC_TF32, en);
                mma_tf32_ss(tmem + 128, a0 + o, b1 + o, IDESC_TF32, en);
                mma_tf32_ss(tmem + 256, a1 + o, b0 + o, IDESC_TF32, en);
                mma_tf32_ss(tmem + 384, a1 + o, b1 + o, IDESC_TF32, en);
            }
            mma_commit(mb_done + 8 * slot);
        }
        mma_commit(mbarF);
    }

    // ---------------- epilogue (all 128 threads) ----------------
    mbar_wait(mbarF, 0);
    tc_fence_after();

    #pragma unroll
    for (int blk = 0; blk < 2; blk++) {
        const int grow = row0 + blk * 128 + wid * 32 + lid;
        float* crow = C + (long long)grow * ldc + col0;
        #pragma unroll
        for (int cb = 0; cb < 8; cb++) {
            u32 r[32];
            tmem_ld32(r, tmem + blk * 256 + cb * 32);
            tmem_wait_ld();
            #pragma unroll
            for (int jj = 0; jj < 32; jj += 4) {
                float4 t;
                t.x = alpha * __uint_as_float(r[jj + 0]);
                t.y = alpha * __uint_as_float(r[jj + 1]);
                t.z = alpha * __uint_as_float(r[jj + 2]);
                t.w = alpha * __uint_as_float(r[jj + 3]);
                *(float4*)(crow + cb * 32 + jj) = t;
            }
        }
    }

    __syncthreads();
    if (wid == 0) tmem_dealloc(tmem, 512);
#endif  // HAS_TCGEN05
}

// ---------------------------------------------------------------------------
__global__ __launch_bounds__(256) void round_tf32_vec(
    const float* __restrict__ src, float* __restrict__ dst)
{
    const long long i = ((long long)blockIdx.x * 256 + threadIdx.x) * 4;
    float4 t = *(const float4*)(src + i);
    uint4 u;
    u.x = cvt_tf32(t.x); u.y = cvt_tf32(t.y);
    u.z = cvt_tf32(t.z); u.w = cvt_tf32(t.w);
    *(uint4*)(dst + i) = u;
}

__global__ __launch_bounds__(256) void transpose_round(
    const float* __restrict__ src, float* __restrict__ dst, int R, int C)
{
    __shared__ float t[32][33];
    const long long boff = (long long)blockIdx.z * R * C;
    src += boff; dst += boff;
    const int r0 = blockIdx.y * 32, c0 = blockIdx.x * 32;
    const int tx = threadIdx.x, ty = threadIdx.y;   // (32, 8)
    #pragma unroll
    for (int i = 0; i < 4; i++)
        t[ty + 8 * i][tx] = src[(long long)(r0 + ty + 8 * i) * C + c0 + tx];
    __syncthreads();
    #pragma unroll
    for (int i = 0; i < 4; i++)
        dst[(long long)(c0 + ty + 8 * i) * R + r0 + tx] =
            __uint_as_float(cvt_tf32(t[tx][ty + 8 * i]));
}

__global__ __launch_bounds__(256) void softmax_rows(float* __restrict__ scores)
{
    const long long row = blockIdx.x;
    float* p = scores + row * (long long)ATT_S;
    const int tid = threadIdx.x;

    float v[8];
    float m = -CUDART_INF_F;
    #pragma unroll
    for (int i = 0; i < 8; i++) {
        v[i] = p[tid + i * 256];
        m = fmaxf(m, v[i]);
    }
    __shared__ float red[8];
    #pragma unroll
    for (int o = 16; o > 0; o >>= 1)
        m = fmaxf(m, __shfl_xor_sync(0xffffffffu, m, o));
    if ((tid & 31) == 0) red[tid >> 5] = m;
    __syncthreads();
    float bm = red[0];
    #pragma unroll
    for (int i = 1; i < 8; i++) bm = fmaxf(bm, red[i]);
    __syncthreads();

    float s = 0.0f;
    #pragma unroll
    for (int i = 0; i < 8; i++) {
        v[i] = __expf(v[i] - bm);
        s += v[i];
    }
    #pragma unroll
    for (int o = 16; o > 0; o >>= 1)
        s += __shfl_xor_sync(0xffffffffu, s, o);
    if ((tid & 31) == 0) red[tid >> 5] = s;
    __syncthreads();
    float total = 0.0f;
    #pragma unroll
    for (int i = 0; i < 8; i++) total += red[i];

    float inv = 1.0f / total;
    #pragma unroll
    for (int i = 0; i < 8; i++)
        p[tid + i * 256] = __uint_as_float(cvt_tf32(v[i] * inv));
}

// ---------------------------------------------------------------------------
// Host: tensor-map construction via driver entry point (no -lcuda needed).
// ---------------------------------------------------------------------------
typedef CUresult (*EncodeTiledFn)(
    CUtensorMap*, CUtensorMapDataType, cuuint32_t, void*,
    const cuuint64_t*, const cuuint64_t*, const cuuint32_t*, const cuuint32_t*,
    CUtensorMapInterleave, CUtensorMapSwizzle, CUtensorMapL2promotion,
    CUtensorMapFloatOOBfill);

static void make_map(EncodeTiledFn enc, CUtensorMap* tm, void* base,
                     long long ld, long long rows, int batch)
{
    cuuint64_t dims[3]    = {(cuuint64_t)ld, (cuuint64_t)rows, (cuuint64_t)batch};
    cuuint64_t strides[2] = {(cuuint64_t)(ld * 4), (cuuint64_t)(rows * ld * 4)};
    cuuint32_t box[3]     = {32, 256, 1};
    cuuint32_t estr[3]    = {1, 1, 1};
    enc(tm, CU_TENSOR_MAP_DATA_TYPE_FLOAT32, 3, base, dims, strides, box, estr,
        CU_TENSOR_MAP_INTERLEAVE_NONE, CU_TENSOR_MAP_SWIZZLE_128B,
        CU_TENSOR_MAP_L2_PROMOTION_L2_128B, CU_TENSOR_MAP_FLOAT_OOB_FILL_NONE);
}

extern "C" void kernel_launch(void* const* d_in, const int* in_sizes, int n_in,
                              void* d_out, int out_size)
{
    const float* q = (const float*)d_in[0];   // [B, S, D]
    const float* k = (const float*)d_in[1];   // [B, D, S]
    const float* v = (const float*)d_in[2];   // [B, S, Dv]
    float* out = (float*)d_out;               // [B, S, Dv]

    float *scores, *qr, *kT, *vT;
    cudaGetSymbolAddress((void**)&scores, g_scores);
    cudaGetSymbolAddress((void**)&qr, g_qr);
    cudaGetSymbolAddress((void**)&kT, g_kT);
    cudaGetSymbolAddress((void**)&vT, g_vT);

    const int B = ATT_B, S = ATT_S, D = ATT_D;

    // Driver entry point for cuTensorMapEncodeTiled (header types, no -lcuda)
    void* encp = nullptr;
    cudaDriverEntryPointQueryResult qres;
    cudaGetDriverEntryPointByVersion("cuTensorMapEncodeTiled", &encp, 12000,
                                     cudaEnableDefault, &qres);
    EncodeTiledFn enc = (EncodeTiledFn)encp;

    CUtensorMap tmQ, tmK, tmP, tmV;
    make_map(enc, &tmQ, qr,     D, S, B);   // A of GEMM1: [B][S rows][D]
    make_map(enc, &tmK, kT,     D, S, B);   // B of GEMM1: [B][S rows][D]
    make_map(enc, &tmP, scores, S, S, B);   // A of GEMM2: [B][S rows][S]
    make_map(enc, &tmV, vT,     S, D, B);   // B of GEMM2: [B][D rows][S]

    cudaFuncSetAttribute(gemm_tf32_tma,
                         cudaFuncAttributeMaxDynamicSharedMemorySize, SMEM_DYN);

    {
        long long nq = (long long)B * S * D;
        round_tf32_vec<<<(unsigned)(nq / (256 * 4)), 256>>>(q, qr);
        dim3 blk(32, 8);
        transpose_round<<<dim3(S / 32, D / 32, B), blk>>>(k, kT, D, S);
        transpose_round<<<dim3(D / 32, S / 32, B), blk>>>(v, vT, S, D);
    }

    {   // scores = 0.1 * qr @ kT^T : M=S, N=S, K=D
        dim3 grid(S / TN_TILE, S / TM_TILE, B);
        gemm_tf32_tma<<<grid, 128, SMEM_DYN>>>(tmQ, tmK, scores,
                                               D, S, 0.1f, (long long)S * S);
    }
    {
        softmax_rows<<<B * S, 256>>>(scores);
    }
    {   // out = scores @ vT^T : M=S, N=D, K=S
        dim3 grid(D / TN_TILE, S / TM_TILE, B);
        gemm_tf32_tma<<<grid, 128, SMEM_DYN>>>(tmP, tmV, out,
                                               S, D, 1.0f, (long long)S * D);
    }
}

// round 11
// speedup vs baseline: 1.1932x; 1.1932x over previous
#include <cuda_runtime.h>
#include <math_constants.h>
#include <cstdint>

typedef unsigned int u32;
typedef unsigned long long u64;

// r = softmax( (q @ k) * 0.1 , -1) @ v ; B=8, S=2048, D=Dv=1024, fp32.
// Round 11: deepen pipeline. TK=16 fp32 (64B rows, SW64 swizzle) ->
// 32KB stages, 6-stage ring, 4-deep cp.async. 256x256 tile, tcgen05 tf32.

#if defined(__CUDA_ARCH_FEAT_SM103_ALL) || defined(__CUDA_ARCH_FEAT_SM100_ALL) || \
    defined(__CUDA_ARCH_SPECIFIC__)
#define HAS_TCGEN05 1
#else
#define HAS_TCGEN05 0
#endif

#define ATT_B 8
#define ATT_S 2048
#define ATT_D 1024

__device__ float g_scores[(size_t)ATT_B * ATT_S * ATT_S];
__device__ float g_qr[(size_t)ATT_B * ATT_S * ATT_D];
__device__ float g_kT[(size_t)ATT_B * ATT_S * ATT_D];
__device__ float g_vT[(size_t)ATT_B * ATT_D * ATT_S];

// ---------------- PTX helpers ----------------
__device__ __forceinline__ u32 smem_u32(const void* p) {
    u32 a;
    asm("{ .reg .u64 t; cvta.to.shared.u64 t, %1; cvt.u32.u64 %0, t; }"
        : "=r"(a) : "l"(p));
    return a;
}
__device__ __forceinline__ u32 elect1() {
    u32 p;
    asm volatile("{ .reg .pred p; elect.sync _|p, 0xFFFFFFFF; selp.b32 %0,1,0,p; }"
                 : "=r"(p));
    return p;
}
__device__ __forceinline__ u32 cvt_tf32(float x) {
    u32 r;
    asm("cvt.rn.tf32.f32 %0, %1;" : "=r"(r) : "f"(x));
    return r;
}
__device__ __forceinline__ void mbar_init(u32 mbar, u32 cnt) {
    asm volatile("mbarrier.init.shared.b64 [%0], %1;" :: "r"(mbar), "r"(cnt) : "memory");
}
__device__ __forceinline__ void mbar_wait(u32 mbar, u32 parity) {
    asm volatile(
        "{ .reg .pred P;\n"
        "L%=: mbarrier.try_wait.parity.acquire.cta.shared::cta.b64 P, [%0], %1, 0x989680;\n"
        "@P bra D%=;\n"
        "bra L%=;\n"
        "D%=: }\n"
        :: "r"(mbar), "r"(parity) : "memory");
}
__device__ __forceinline__ void cp_async16(u32 dst, const void* src) {
    asm volatile("cp.async.cg.shared.global [%0], [%1], 16;"
                 :: "r"(dst), "l"(src) : "memory");
}
__device__ __forceinline__ void cp_commit() {
    asm volatile("cp.async.commit_group;" ::: "memory");
}
__device__ __forceinline__ void cp_wait3() {
    asm volatile("cp.async.wait_group 3;" ::: "memory");
}
__device__ __forceinline__ void fence_async_proxy() {
    asm volatile("fence.proxy.async.shared::cta;" ::: "memory");
}

#if HAS_TCGEN05
__device__ __forceinline__ void tmem_alloc(u32 smem_dst, u32 ncols) {
    asm volatile("tcgen05.alloc.cta_group::1.sync.aligned.shared::cta.b32 [%0], %1;"
                 :: "r"(smem_dst), "r"(ncols) : "memory");
}
__device__ __forceinline__ void tmem_relinquish() {
    asm volatile("tcgen05.relinquish_alloc_permit.cta_group::1.sync.aligned;");
}
__device__ __forceinline__ void tmem_dealloc(u32 tmem, u32 ncols) {
    asm volatile("tcgen05.dealloc.cta_group::1.sync.aligned.b32 %0, %1;"
                 :: "r"(tmem), "r"(ncols));
}
__device__ __forceinline__ void mma_tf32_ss(u32 d_tmem, u64 ad, u64 bd, u32 idesc, u32 en) {
    asm volatile(
        "{ .reg .pred p; setp.ne.u32 p, %4, 0;\n"
        "tcgen05.mma.cta_group::1.kind::tf32 [%0], %1, %2, %3, {%5,%5,%5,%5}, p;\n }"
        :: "r"(d_tmem), "l"(ad), "l"(bd), "r"(idesc), "r"(en), "r"(0u) : "memory");
}
__device__ __forceinline__ void mma_commit(u32 mbar) {
    asm volatile(
        "tcgen05.commit.cta_group::1.mbarrier::arrive::one.shared::cluster.b64 [%0];"
        :: "r"(mbar) : "memory");
}
__device__ __forceinline__ void tc_fence_after() {
    asm volatile("tcgen05.fence::after_thread_sync;" ::: "memory");
}
__device__ __forceinline__ void tmem_ld32(u32* r, u32 tmem) {
    asm volatile(
        "tcgen05.ld.sync.aligned.32x32b.x32.b32 "
        "{%0,%1,%2,%3,%4,%5,%6,%7,%8,%9,%10,%11,%12,%13,%14,%15,"
        "%16,%17,%18,%19,%20,%21,%22,%23,%24,%25,%26,%27,%28,%29,%30,%31}, [%32];"
        : "=r"(r[0]), "=r"(r[1]), "=r"(r[2]), "=r"(r[3]),
          "=r"(r[4]), "=r"(r[5]), "=r"(r[6]), "=r"(r[7]),
          "=r"(r[8]), "=r"(r[9]), "=r"(r[10]), "=r"(r[11]),
          "=r"(r[12]), "=r"(r[13]), "=r"(r[14]), "=r"(r[15]),
          "=r"(r[16]), "=r"(r[17]), "=r"(r[18]), "=r"(r[19]),
          "=r"(r[20]), "=r"(r[21]), "=r"(r[22]), "=r"(r[23]),
          "=r"(r[24]), "=r"(r[25]), "=r"(r[26]), "=r"(r[27]),
          "=r"(r[28]), "=r"(r[29]), "=r"(r[30]), "=r"(r[31])
        : "r"(tmem));
}
__device__ __forceinline__ void tmem_wait_ld() {
    asm volatile("tcgen05.wait::ld.sync.aligned;" ::: "memory");
}
#endif  // HAS_TCGEN05

// SW64 swizzle: XOR bits [5:4] with bits [8:7] (atom = 8 rows x 64B)
#define SW64(o) ((o) ^ (((o) >> 3) & 0x30))

// SW64 K-major SMEM descriptor: layout=4, version=1, SBO=32, LBO=1
static constexpr u64 DESC_BASE_SW64 =
    (4ull << 61) | (1ull << 46) | (32ull << 32) | (1ull << 16);
__device__ __forceinline__ u64 mk_desc(u32 addr) {
    return DESC_BASE_SW64 | ((u64)(addr >> 4) & 0x3FFF);
}

// idesc kind::tf32: dtype=F32, atype=btype=TF32, N=128, M=128
static constexpr u32 IDESC_TF32 =
    (1u << 4) | (2u << 7) | (2u << 10) | ((128u / 8) << 17) | ((128u / 16) << 24);

#define TK 16                   // fp32 per row (64B rows, SW64)
#define TM_TILE 256
#define TN_TILE 256
#define A_BYTES 16384           // 256 rows x 64B
#define B_BYTES 16384
#define STAGE_BYTES (A_BYTES + B_BYTES)   // 32KB
#define STAGES 6
#define PRELOAD 4               // wait_group 3
#define SMEM_CTRL 2048
#define SMEM_DYN (SMEM_CTRL + STAGES * STAGE_BYTES)   // 198,656 B

// ---------------------------------------------------------------------------
// tcgen05 tf32 batched GEMM:  C[M,N] = alpha * A[M,K] @ BT[N,K]^T
// 256x256 tile per CTA, TK=16, SW64 tiles.
// ---------------------------------------------------------------------------
__global__ __launch_bounds__(128) void gemm_tf32_pipe(
    const float* __restrict__ A, const float* __restrict__ BT,
    float* __restrict__ C, int K, int lda, int ldbt, int ldc, float alpha,
    long long strideA, long long strideB, long long strideC)
{
#if HAS_TCGEN05
    extern __shared__ char smem[];
    const u32 smem_base = smem_u32(smem);
    const u32 tiles_addr = (smem_base + 1024 + 1023) & ~1023u;

    const int tid = threadIdx.x;
    const int wid = tid >> 5;
    const int lid = tid & 31;

    const int b = blockIdx.z;
    A  += (long long)b * strideA;
    BT += (long long)b * strideB;
    C  += (long long)b * strideC;

    const int row0 = blockIdx.y * TM_TILE;
    const int col0 = blockIdx.x * TN_TILE;

    const u32 mbar0 = smem_base + 8;       // STAGES slot barriers (MMA done)
    const u32 mbarF = smem_base + 8 + 8 * STAGES;

    if (tid == 0) {
        #pragma unroll
        for (int s = 0; s < STAGES; s++) mbar_init(mbar0 + 8 * s, 1);
        mbar_init(mbarF, 1);
    }
    if (wid == 0) {
        tmem_alloc(smem_base + 0, 512);
        tmem_relinquish();
    }
    __syncthreads();
    u32 tmem;
    asm volatile("ld.shared.b32 %0, [%1];" : "=r"(tmem) : "r"(smem_base + 0));

    // per-thread load mapping: 4 chunks of 16B per 64B row
    const int c16   = tid & 3;      // 16B chunk within 64B row
    const int rbase = tid >> 2;     // 0..31

    const float* Abase = A  + (long long)(row0 + rbase) * lda  + c16 * 4;
    const float* Bbase = BT + (long long)(col0 + rbase) * ldbt + c16 * 4;

    const int KT = K / TK;
    u32 phases = 0;

    auto load_tile = [&](int kt) {
        const int slot = kt % STAGES;
        const u32 At = tiles_addr + slot * STAGE_BYTES;
        const u32 Bt = At + A_BYTES;
        const float* as = Abase + kt * TK;
        const float* bs = Bbase + kt * TK;
        #pragma unroll
        for (int p = 0; p < 8; p++) {      // A: 256 rows, stride 32
            const int r = rbase + p * 32;
            cp_async16(At + SW64((u32)(r * 64 + c16 * 16)),
                       as + (long long)(p * 32) * lda);
        }
        #pragma unroll
        for (int p = 0; p < 8; p++) {      // B: 256 rows
            const int r = rbase + p * 32;
            cp_async16(Bt + SW64((u32)(r * 64 + c16 * 16)),
                       bs + (long long)(p * 32) * ldbt);
        }
        cp_commit();
    };

    #pragma unroll
    for (int t = 0; t < PRELOAD; t++) load_tile(t);

    for (int i = 0; i < KT; i++) {
        // commits so far = PRELOAD + i ; pending <= 3 => tile i landed
        cp_wait3();
        fence_async_proxy();
        __syncthreads();

        if (wid == 0 && elect1()) {
            const int slot = i % STAGES;
            const u32 At = tiles_addr + slot * STAGE_BYTES;
            const u64 a0 = mk_desc(At);                     // A rows 0..127
            const u64 a1 = mk_desc(At + 8192);              // A rows 128..255
            const u64 b0 = mk_desc(At + A_BYTES);           // B rows 0..127
            const u64 b1 = mk_desc(At + A_BYTES + 8192);    // B rows 128..255
            #pragma unroll
            for (int sub = 0; sub < 2; sub++) {             // 2 x K=8 steps
                const u32 en = (i | sub) != 0;
                const u64 o = sub * 2;                      // +32B per K=8
                mma_tf32_ss(tmem,       a0 + o, b0 + o, IDESC_TF32, en);
                mma_tf32_ss(tmem + 128, a0 + o, b1 + o, IDESC_TF32, en);
                mma_tf32_ss(tmem + 256, a1 + o, b0 + o, IDESC_TF32, en);
                mma_tf32_ss(tmem + 384, a1 + o, b1 + o, IDESC_TF32, en);
            }
            mma_commit(mbar0 + 8 * slot);
        }

        const int j = i + PRELOAD;
        if (j < KT) {
            // slot j%STAGES previously held tile j-STAGES = i-2
            if (i >= 2) {
                const int s = (i - 2) % STAGES;
                mbar_wait(mbar0 + 8 * s, (phases >> s) & 1);
                phases ^= (1u << s);
            }
            load_tile(j);
        } else {
            cp_commit();   // empty group keeps wait_group accounting exact
        }
    }

    if (wid == 0 && elect1()) mma_commit(mbarF);
    mbar_wait(mbarF, 0);
    tc_fence_after();

    // epilogue: 2 row blocks; warp w -> lanes w*32..w*32+31 of each block
    #pragma unroll
    for (int blk = 0; blk < 2; blk++) {
        const int grow = row0 + blk * 128 + wid * 32 + lid;
        float* crow = C + (long long)grow * ldc + col0;
        #pragma unroll
        for (int cb = 0; cb < 8; cb++) {
            u32 r[32];
            tmem_ld32(r, tmem + blk * 256 + cb * 32);
            tmem_wait_ld();
            #pragma unroll
            for (int jj = 0; jj < 32; jj += 4) {
                float4 t;
                t.x = alpha * __uint_as_float(r[jj + 0]);
                t.y = alpha * __uint_as_float(r[jj + 1]);
                t.z = alpha * __uint_as_float(r[jj + 2]);
                t.w = alpha * __uint_as_float(r[jj + 3]);
                *(float4*)(crow + cb * 32 + jj) = t;
            }
        }
    }

    __syncthreads();
    if (wid == 0) tmem_dealloc(tmem, 512);
#endif  // HAS_TCGEN05
}

// ---------------------------------------------------------------------------
__global__ __launch_bounds__(256) void round_tf32_vec(
    const float* __restrict__ src, float* __restrict__ dst)
{
    const long long i = ((long long)blockIdx.x * 256 + threadIdx.x) * 4;
    float4 t = *(const float4*)(src + i);
    uint4 u;
    u.x = cvt_tf32(t.x); u.y = cvt_tf32(t.y);
    u.z = cvt_tf32(t.z); u.w = cvt_tf32(t.w);
    *(uint4*)(dst + i) = u;
}

__global__ __launch_bounds__(256) void transpose_round(
    const float* __restrict__ src, float* __restrict__ dst, int R, int C)
{
    __shared__ float t[32][33];
    const long long boff = (long long)blockIdx.z * R * C;
    src += boff; dst += boff;
    const int r0 = blockIdx.y * 32, c0 = blockIdx.x * 32;
    const int tx = threadIdx.x, ty = threadIdx.y;   // (32, 8)
    #pragma unroll
    for (int i = 0; i < 4; i++)
        t[ty + 8 * i][tx] = src[(long long)(r0 + ty + 8 * i) * C + c0 + tx];
    __syncthreads();
    #pragma unroll
    for (int i = 0; i < 4; i++)
        dst[(long long)(c0 + ty + 8 * i) * R + r0 + tx] =
            __uint_as_float(cvt_tf32(t[tx][ty + 8 * i]));
}

__global__ __launch_bounds__(256) void softmax_rows(float* __restrict__ scores)
{
    const long long row = blockIdx.x;
    float* p = scores + row * (long long)ATT_S;
    const int tid = threadIdx.x;

    float v[8];
    float m = -CUDART_INF_F;
    #pragma unroll
    for (int i = 0; i < 8; i++) {
        v[i] = p[tid + i * 256];
        m = fmaxf(m, v[i]);
    }
    __shared__ float red[8];
    #pragma unroll
    for (int o = 16; o > 0; o >>= 1)
        m = fmaxf(m, __shfl_xor_sync(0xffffffffu, m, o));
    if ((tid & 31) == 0) red[tid >> 5] = m;
    __syncthreads();
    float bm = red[0];
    #pragma unroll
    for (int i = 1; i < 8; i++) bm = fmaxf(bm, red[i]);
    __syncthreads();

    float s = 0.0f;
    #pragma unroll
    for (int i = 0; i < 8; i++) {
        v[i] = __expf(v[i] - bm);
        s += v[i];
    }
    #pragma unroll
    for (int o = 16; o > 0; o >>= 1)
        s += __shfl_xor_sync(0xffffffffu, s, o);
    if ((tid & 31) == 0) red[tid >> 5] = s;
    __syncthreads();
    float total = 0.0f;
    #pragma unroll
    for (int i = 0; i < 8; i++) total += red[i];

    float inv = 1.0f / total;
    #pragma unroll
    for (int i = 0; i < 8; i++)
        p[tid + i * 256] = __uint_as_float(cvt_tf32(v[i] * inv));
}

// ---------------------------------------------------------------------------
extern "C" void kernel_launch(void* const* d_in, const int* in_sizes, int n_in,
                              void* d_out, int out_size)
{
    const float* q = (const float*)d_in[0];   // [B, S, D]
    const float* k = (const float*)d_in[1];   // [B, D, S]
    const float* v = (const float*)d_in[2];   // [B, S, Dv]
    float* out = (float*)d_out;               // [B, S, Dv]

    float *scores, *qr, *kT, *vT;
    cudaGetSymbolAddress((void**)&scores, g_scores);
    cudaGetSymbolAddress((void**)&qr, g_qr);
    cudaGetSymbolAddress((void**)&kT, g_kT);
    cudaGetSymbolAddress((void**)&vT, g_vT);

    const int B = ATT_B, S = ATT_S, D = ATT_D;

    cudaFuncSetAttribute(gemm_tf32_pipe,
                         cudaFuncAttributeMaxDynamicSharedMemorySize, SMEM_DYN);

    {
        long long nq = (long long)B * S * D;
        round_tf32_vec<<<(unsigned)(nq / (256 * 4)), 256>>>(q, qr);
        dim3 blk(32, 8);
        transpose_round<<<dim3(S / 32, D / 32, B), blk>>>(k, kT, D, S);
        transpose_round<<<dim3(D / 32, S / 32, B), blk>>>(v, vT, S, D);
    }

    {   // scores = 0.1 * qr @ kT^T : M=S, N=S, K=D
        dim3 grid(S / TN_TILE, S / TM_TILE, B);
        gemm_tf32_pipe<<<grid, 128, SMEM_DYN>>>(qr, kT, scores,
                                                D, D, D, S, 0.1f,
                                                (long long)S * D, (long long)S * D,
                                                (long long)S * S);
    }
    {
        softmax_rows<<<B * S, 256>>>(scores);
    }
    {   // out = scores @ vT^T : M=S, N=D, K=S
        dim3 grid(D / TN_TILE, S / TM_TILE, B);
        gemm_tf32_pipe<<<grid, 128, SMEM_DYN>>>(scores, vT, out,
                                                S, S, S, D, 1.0f,
                                                (long long)S * S, (long long)D * S,
                                                (long long)S * D);
    }
}

// round 13
// speedup vs baseline: 1.3180x; 1.1046x over previous
#include <cuda_runtime.h>
#include <math_constants.h>
#include <cstdint>

typedef unsigned int u32;
typedef unsigned long long u64;

// r = softmax( (q @ k) * 0.1 , -1) @ v ; B=8, S=2048, D=Dv=1024, fp32.
// Round 12: R8 structure (256x256 tile, TK=32, 3x64KB stages, PRELOAD=2)
// with 256 threads: 2x cp.async parallelism, 2x epilogue warps.

#if defined(__CUDA_ARCH_FEAT_SM103_ALL) || defined(__CUDA_ARCH_FEAT_SM100_ALL) || \
    defined(__CUDA_ARCH_SPECIFIC__)
#define HAS_TCGEN05 1
#else
#define HAS_TCGEN05 0
#endif

#define ATT_B 8
#define ATT_S 2048
#define ATT_D 1024

__device__ float g_scores[(size_t)ATT_B * ATT_S * ATT_S];
__device__ float g_qr[(size_t)ATT_B * ATT_S * ATT_D];
__device__ float g_kT[(size_t)ATT_B * ATT_S * ATT_D];
__device__ float g_vT[(size_t)ATT_B * ATT_D * ATT_S];

// ---------------- PTX helpers ----------------
__device__ __forceinline__ u32 smem_u32(const void* p) {
    u32 a;
    asm("{ .reg .u64 t; cvta.to.shared.u64 t, %1; cvt.u32.u64 %0, t; }"
        : "=r"(a) : "l"(p));
    return a;
}
__device__ __forceinline__ u32 elect1() {
    u32 p;
    asm volatile("{ .reg .pred p; elect.sync _|p, 0xFFFFFFFF; selp.b32 %0,1,0,p; }"
                 : "=r"(p));
    return p;
}
__device__ __forceinline__ u32 cvt_tf32(float x) {
    u32 r;
    asm("cvt.rn.tf32.f32 %0, %1;" : "=r"(r) : "f"(x));
    return r;
}
__device__ __forceinline__ void mbar_init(u32 mbar, u32 cnt) {
    asm volatile("mbarrier.init.shared.b64 [%0], %1;" :: "r"(mbar), "r"(cnt) : "memory");
}
__device__ __forceinline__ void mbar_wait(u32 mbar, u32 parity) {
    asm volatile(
        "{ .reg .pred P;\n"
        "L%=: mbarrier.try_wait.parity.acquire.cta.shared::cta.b64 P, [%0], %1, 0x989680;\n"
        "@P bra D%=;\n"
        "bra L%=;\n"
        "D%=: }\n"
        :: "r"(mbar), "r"(parity) : "memory");
}
__device__ __forceinline__ void cp_async16(u32 dst, const void* src) {
    asm volatile("cp.async.cg.shared.global [%0], [%1], 16;"
                 :: "r"(dst), "l"(src) : "memory");
}
__device__ __forceinline__ void cp_commit() {
    asm volatile("cp.async.commit_group;" ::: "memory");
}
__device__ __forceinline__ void cp_wait1() {
    asm volatile("cp.async.wait_group 1;" ::: "memory");
}
__device__ __forceinline__ void fence_async_proxy() {
    asm volatile("fence.proxy.async.shared::cta;" ::: "memory");
}

#if HAS_TCGEN05
__device__ __forceinline__ void tmem_alloc(u32 smem_dst, u32 ncols) {
    asm volatile("tcgen05.alloc.cta_group::1.sync.aligned.shared::cta.b32 [%0], %1;"
                 :: "r"(smem_dst), "r"(ncols) : "memory");
}
__device__ __forceinline__ void tmem_relinquish() {
    asm volatile("tcgen05.relinquish_alloc_permit.cta_group::1.sync.aligned;");
}
__device__ __forceinline__ void tmem_dealloc(u32 tmem, u32 ncols) {
    asm volatile("tcgen05.dealloc.cta_group::1.sync.aligned.b32 %0, %1;"
                 :: "r"(tmem), "r"(ncols));
}
__device__ __forceinline__ void mma_tf32_ss(u32 d_tmem, u64 ad, u64 bd, u32 idesc, u32 en) {
    asm volatile(
        "{ .reg .pred p; setp.ne.u32 p, %4, 0;\n"
        "tcgen05.mma.cta_group::1.kind::tf32 [%0], %1, %2, %3, {%5,%5,%5,%5}, p;\n }"
        :: "r"(d_tmem), "l"(ad), "l"(bd), "r"(idesc), "r"(en), "r"(0u) : "memory");
}
__device__ __forceinline__ void mma_commit(u32 mbar) {
    asm volatile(
        "tcgen05.commit.cta_group::1.mbarrier::arrive::one.shared::cluster.b64 [%0];"
        :: "r"(mbar) : "memory");
}
__device__ __forceinline__ void tc_fence_after() {
    asm volatile("tcgen05.fence::after_thread_sync;" ::: "memory");
}
__device__ __forceinline__ void tmem_ld32(u32* r, u32 tmem) {
    asm volatile(
        "tcgen05.ld.sync.aligned.32x32b.x32.b32 "
        "{%0,%1,%2,%3,%4,%5,%6,%7,%8,%9,%10,%11,%12,%13,%14,%15,"
        "%16,%17,%18,%19,%20,%21,%22,%23,%24,%25,%26,%27,%28,%29,%30,%31}, [%32];"
        : "=r"(r[0]), "=r"(r[1]), "=r"(r[2]), "=r"(r[3]),
          "=r"(r[4]), "=r"(r[5]), "=r"(r[6]), "=r"(r[7]),
          "=r"(r[8]), "=r"(r[9]), "=r"(r[10]), "=r"(r[11]),
          "=r"(r[12]), "=r"(r[13]), "=r"(r[14]), "=r"(r[15]),
          "=r"(r[16]), "=r"(r[17]), "=r"(r[18]), "=r"(r[19]),
          "=r"(r[20]), "=r"(r[21]), "=r"(r[22]), "=r"(r[23]),
          "=r"(r[24]), "=r"(r[25]), "=r"(r[26]), "=r"(r[27]),
          "=r"(r[28]), "=r"(r[29]), "=r"(r[30]), "=r"(r[31])
        : "r"(tmem));
}
__device__ __forceinline__ void tmem_wait_ld() {
    asm volatile("tcgen05.wait::ld.sync.aligned;" ::: "memory");
}
#endif  // HAS_TCGEN05

#define SW128(o) ((o) ^ (((o) >> 3) & 0x70))

static constexpr u64 DESC_BASE =
    (2ull << 61) | (1ull << 46) | (64ull << 32) | (1ull << 16);
__device__ __forceinline__ u64 mk_desc(u32 addr) {
    return DESC_BASE | ((u64)(addr >> 4) & 0x3FFF);
}

// idesc kind::tf32: dtype=F32, atype=btype=TF32, N=128, M=128
static constexpr u32 IDESC_TF32 =
    (1u << 4) | (2u << 7) | (2u << 10) | ((128u / 8) << 17) | ((128u / 16) << 24);

#define TK 32
#define TM_TILE 256
#define TN_TILE 256
#define A_BYTES 32768
#define B_BYTES 32768
#define STAGE_BYTES (A_BYTES + B_BYTES)   // 64KB
#define STAGES 3
#define PRELOAD 2
#define NTHREADS 256
#define SMEM_CTRL 2048
#define SMEM_DYN (SMEM_CTRL + STAGES * STAGE_BYTES)   // 198,656 B

// ---------------------------------------------------------------------------
// tcgen05 tf32 batched GEMM:  C[M,N] = alpha * A[M,K] @ BT[N,K]^T
// 256x256 tile per CTA; 256 threads.
// ---------------------------------------------------------------------------
__global__ __launch_bounds__(NTHREADS) void gemm_tf32_pipe(
    const float* __restrict__ A, const float* __restrict__ BT,
    float* __restrict__ C, int K, int lda, int ldbt, int ldc, float alpha,
    long long strideA, long long strideB, long long strideC)
{
#if HAS_TCGEN05
    extern __shared__ char smem[];
    const u32 smem_base = smem_u32(smem);
    const u32 tiles_addr = (smem_base + 1024 + 1023) & ~1023u;

    const int tid = threadIdx.x;
    const int wid = tid >> 5;
    const int lid = tid & 31;

    const int b = blockIdx.z;
    A  += (long long)b * strideA;
    BT += (long long)b * strideB;
    C  += (long long)b * strideC;

    const int row0 = blockIdx.y * TM_TILE;
    const int col0 = blockIdx.x * TN_TILE;

    const u32 mbar0 = smem_base + 8;       // STAGES slot barriers (MMA done)
    const u32 mbarF = smem_base + 8 + 8 * STAGES;

    if (tid == 0) {
        #pragma unroll
        for (int s = 0; s < STAGES; s++) mbar_init(mbar0 + 8 * s, 1);
        mbar_init(mbarF, 1);
    }
    if (wid == 0) {
        tmem_alloc(smem_base + 0, 512);
        tmem_relinquish();
    }
    __syncthreads();
    u32 tmem;
    asm volatile("ld.shared.b32 %0, [%1];" : "=r"(tmem) : "r"(smem_base + 0));

    // per-thread load mapping: 8 chunks of 16B per 128B row; 32 row-groups
    const int c16   = tid & 7;      // 16B chunk within 128B row
    const int rbase = tid >> 3;     // 0..31

    const float* Abase = A  + (long long)(row0 + rbase) * lda  + c16 * 4;
    const float* Bbase = BT + (long long)(col0 + rbase) * ldbt + c16 * 4;

    const int KT = K / TK;
    u32 phases = 0;

    auto load_tile = [&](int kt) {
        const int slot = kt % STAGES;
        const u32 At = tiles_addr + slot * STAGE_BYTES;
        const u32 Bt = At + A_BYTES;
        const float* as = Abase + kt * TK;
        const float* bs = Bbase + kt * TK;
        #pragma unroll
        for (int p = 0; p < 8; p++) {      // A: 256 rows, stride 32
            const int r = rbase + p * 32;
            cp_async16(At + SW128((u32)(r * 128 + c16 * 16)),
                       as + (long long)(p * 32) * lda);
        }
        #pragma unroll
        for (int p = 0; p < 8; p++) {      // B: 256 rows
            const int r = rbase + p * 32;
            cp_async16(Bt + SW128((u32)(r * 128 + c16 * 16)),
                       bs + (long long)(p * 32) * ldbt);
        }
        cp_commit();
    };

    #pragma unroll
    for (int t = 0; t < PRELOAD; t++) load_tile(t);

    for (int i = 0; i < KT; i++) {
        // commits so far = PRELOAD + i ; pending <= 1 => tile i landed
        cp_wait1();
        fence_async_proxy();
        __syncthreads();

        if (wid == 0 && elect1()) {
            const int slot = i % STAGES;
            const u32 At = tiles_addr + slot * STAGE_BYTES;
            const u64 a0 = mk_desc(At);                       // A rows 0..127
            const u64 a1 = mk_desc(At + 16384);               // A rows 128..255
            const u64 b0 = mk_desc(At + A_BYTES);             // B rows 0..127
            const u64 b1 = mk_desc(At + A_BYTES + 16384);     // B rows 128..255
            #pragma unroll
            for (int sub = 0; sub < 4; sub++) {
                const u32 en = (i | sub) != 0;
                const u64 o = sub * 2;
                mma_tf32_ss(tmem,       a0 + o, b0 + o, IDESC_TF32, en);
                mma_tf32_ss(tmem + 128, a0 + o, b1 + o, IDESC_TF32, en);
                mma_tf32_ss(tmem + 256, a1 + o, b0 + o, IDESC_TF32, en);
                mma_tf32_ss(tmem + 384, a1 + o, b1 + o, IDESC_TF32, en);
            }
            mma_commit(mbar0 + 8 * slot);
        }

        const int j = i + PRELOAD;
        if (j < KT) {
            // slot j%STAGES previously held tile j-STAGES = i-1
            if (i >= 1) {
                const int s = (i - 1) % STAGES;
                mbar_wait(mbar0 + 8 * s, (phases >> s) & 1);
                phases ^= (1u << s);
            }
            load_tile(j);
        } else {
            cp_commit();   // empty group keeps wait_group accounting exact
        }
    }

    if (wid == 0 && elect1()) mma_commit(mbarF);
    mbar_wait(mbarF, 0);
    tc_fence_after();

    // epilogue: 8 warps. warp w -> row block w/4, TMEM subpartition w%4.
    {
        const int blk  = wid >> 2;
        const int wsub = wid & 3;
        const int grow = row0 + blk * 128 + wsub * 32 + lid;
        float* crow = C + (long long)grow * ldc + col0;
        #pragma unroll
        for (int cb = 0; cb < 8; cb++) {
            u32 r[32];
            tmem_ld32(r, tmem + blk * 256 + cb * 32);
            tmem_wait_ld();
            #pragma unroll
            for (int jj = 0; jj < 32; jj += 4) {
                float4 t;
                t.x = alpha * __uint_as_float(r[jj + 0]);
                t.y = alpha * __uint_as_float(r[jj + 1]);
                t.z = alpha * __uint_as_float(r[jj + 2]);
                t.w = alpha * __uint_as_float(r[jj + 3]);
                *(float4*)(crow + cb * 32 + jj) = t;
            }
        }
    }

    __syncthreads();
    if (wid == 0) tmem_dealloc(tmem, 512);
#endif  // HAS_TCGEN05
}

// ---------------------------------------------------------------------------
__global__ __launch_bounds__(256) void round_tf32_vec(
    const float* __restrict__ src, float* __restrict__ dst)
{
    const long long i = ((long long)blockIdx.x * 256 + threadIdx.x) * 4;
    float4 t = *(const float4*)(src + i);
    uint4 u;
    u.x = cvt_tf32(t.x); u.y = cvt_tf32(t.y);
    u.z = cvt_tf32(t.z); u.w = cvt_tf32(t.w);
    *(uint4*)(dst + i) = u;
}

__global__ __launch_bounds__(256) void transpose_round(
    const float* __restrict__ src, float* __restrict__ dst, int R, int C)
{
    __shared__ float t[32][33];
    const long long boff = (long long)blockIdx.z * R * C;
    src += boff; dst += boff;
    const int r0 = blockIdx.y * 32, c0 = blockIdx.x * 32;
    const int tx = threadIdx.x, ty = threadIdx.y;   // (32, 8)
    #pragma unroll
    for (int i = 0; i < 4; i++)
        t[ty + 8 * i][tx] = src[(long long)(r0 + ty + 8 * i) * C + c0 + tx];
    __syncthreads();
    #pragma unroll
    for (int i = 0; i < 4; i++)
        dst[(long long)(c0 + ty + 8 * i) * R + r0 + tx] =
            __uint_as_float(cvt_tf32(t[tx][ty + 8 * i]));
}

__global__ __launch_bounds__(256) void softmax_rows(float* __restrict__ scores)
{
    const long long row = blockIdx.x;
    float* p = scores + row * (long long)ATT_S;
    const int tid = threadIdx.x;

    float v[8];
    float m = -CUDART_INF_F;
    #pragma unroll
    for (int i = 0; i < 8; i++) {
        v[i] = p[tid + i * 256];
        m = fmaxf(m, v[i]);
    }
    __shared__ float red[8];
    #pragma unroll
    for (int o = 16; o > 0; o >>= 1)
        m = fmaxf(m, __shfl_xor_sync(0xffffffffu, m, o));
    if ((tid & 31) == 0) red[tid >> 5] = m;
    __syncthreads();
    float bm = red[0];
    #pragma unroll
    for (int i = 1; i < 8; i++) bm = fmaxf(bm, red[i]);
    __syncthreads();

    float s = 0.0f;
    #pragma unroll
    for (int i = 0; i < 8; i++) {
        v[i] = __expf(v[i] - bm);
        s += v[i];
    }
    #pragma unroll
    for (int o = 16; o > 0; o >>= 1)
        s += __shfl_xor_sync(0xffffffffu, s, o);
    if ((tid & 31) == 0) red[tid >> 5] = s;
    __syncthreads();
    float total = 0.0f;
    #pragma unroll
    for (int i = 0; i < 8; i++) total += red[i];

    float inv = 1.0f / total;
    #pragma unroll
    for (int i = 0; i < 8; i++)
        p[tid + i * 256] = __uint_as_float(cvt_tf32(v[i] * inv));
}

// ---------------------------------------------------------------------------
extern "C" void kernel_launch(void* const* d_in, const int* in_sizes, int n_in,
                              void* d_out, int out_size)
{
    const float* q = (const float*)d_in[0];   // [B, S, D]
    const float* k = (const float*)d_in[1];   // [B, D, S]
    const float* v = (const float*)d_in[2];   // [B, S, Dv]
    float* out = (float*)d_out;               // [B, S, Dv]

    float *scores, *qr, *kT, *vT;
    cudaGetSymbolAddress((void**)&scores, g_scores);
    cudaGetSymbolAddress((void**)&qr, g_qr);
    cudaGetSymbolAddress((void**)&kT, g_kT);
    cudaGetSymbolAddress((void**)&vT, g_vT);

    const int B = ATT_B, S = ATT_S, D = ATT_D;

    cudaFuncSetAttribute(gemm_tf32_pipe,
                         cudaFuncAttributeMaxDynamicSharedMemorySize, SMEM_DYN);

    {
        long long nq = (long long)B * S * D;
        round_tf32_vec<<<(unsigned)(nq / (256 * 4)), 256>>>(q, qr);
        dim3 blk(32, 8);
        transpose_round<<<dim3(S / 32, D / 32, B), blk>>>(k, kT, D, S);
        transpose_round<<<dim3(D / 32, S / 32, B), blk>>>(v, vT, S, D);
    }

    {   // scores = 0.1 * qr @ kT^T : M=S, N=S, K=D
        dim3 grid(S / TN_TILE, S / TM_TILE, B);
        gemm_tf32_pipe<<<grid, NTHREADS, SMEM_DYN>>>(qr, kT, scores,
                                                     D, D, D, S, 0.1f,
                                                     (long long)S * D, (long long)S * D,
                                                     (long long)S * S);
    }
    {
        softmax_rows<<<B * S, 256>>>(scores);
    }
    {   // out = scores @ vT^T : M=S, N=D, K=S
        dim3 grid(D / TN_TILE, S / TM_TILE, B);
        gemm_tf32_pipe<<<grid, NTHREADS, SMEM_DYN>>>(scores, vT, out,
                                                     S, S, S, D, 1.0f,
                                                     (long long)S * S, (long long)D * S,
                                                     (long long)S * D);
    }
}